// round 13
// baseline (speedup 1.0000x reference)
#include <cuda_runtime.h>

#define NN 100000
#define EE 1600000
#define NB 98            // ceil(NN/1024)

// ---------------- scratch (device globals; no allocation allowed) ------------
__device__ int                    g_is64;         // edge_index stored as int64?
__device__ int                    g_deg[NN];
__device__ int                    g_base[NN];     // CSR row offsets (exclusive scan)
__device__ int                    g_cur[NN];      // fill cursors
__device__ int                    g_bsum[NB];     // scan block sums
__device__ float                  g_dinv[NN];
__device__ int                    g_esrc[EE];     // src ids bucketed by dst
__device__ __align__(16) float    g_P1[NN * 64];  // x @ W_l1
__device__ __align__(16) float    g_Q1[NN * 64];  // x @ W_r1 + b1
__device__ __align__(16) float    g_H [NN * 64];  // layer-1 output
__device__ __align__(16) float    g_P2[NN * 32];  // h @ W_l2
__device__ __align__(16) float    g_Q2[NN * 32];  // h @ W_r2 + b2

__device__ __forceinline__ float leaky(float v) { return v > 0.f ? v : 0.1f * v; }

// ---------------- dtype detect: int64 edge_index has zero high words ---------
__global__ void k_detect(const int* __restrict__ ei) {
    __shared__ int s[64];
    int t = threadIdx.x;                 // 64 threads
    s[t] = ei[2 * t + 1];                // high word if int64; real value if int32
    __syncthreads();
    if (t == 0) {
        int acc = 0;
        #pragma unroll
        for (int i = 0; i < 64; i++) acc |= s[i];
        g_is64 = (acc == 0) ? 1 : 0;
    }
}

// ---------------- CSR build --------------------------------------------------
__global__ void k_zero() {
    int i = blockIdx.x * 256 + threadIdx.x;
    if (i < NN) g_deg[i] = 0;
}

__global__ void k_deg(const int* __restrict__ ei) {
    int e = blockIdx.x * 256 + threadIdx.x;
    if (e < EE) {
        int dst = g_is64 ? ei[2 * (EE + e)] : ei[EE + e];
        if ((unsigned)dst < NN) atomicAdd(&g_deg[dst], 1);
    }
}

// block-level inclusive scan (Hillis-Steele, 1024 threads) -> exclusive base
__global__ __launch_bounds__(1024)
void k_scanA() {
    __shared__ int s[1024];
    int i = blockIdx.x * 1024 + threadIdx.x;
    int v = (i < NN) ? g_deg[i] : 0;
    s[threadIdx.x] = v;
    __syncthreads();
    #pragma unroll
    for (int off = 1; off < 1024; off <<= 1) {
        int t = (threadIdx.x >= off) ? s[threadIdx.x - off] : 0;
        __syncthreads();
        s[threadIdx.x] += t;
        __syncthreads();
    }
    if (i < NN) g_base[i] = s[threadIdx.x] - v;           // exclusive
    if (threadIdx.x == 1023) g_bsum[blockIdx.x] = s[1023];
}

__global__ void k_scanB() {
    __shared__ int s[128];
    int t = threadIdx.x;
    s[t] = (t < NB) ? g_bsum[t] : 0;
    __syncthreads();
    if (t == 0) {
        int run = 0;
        for (int i = 0; i < NB; i++) { int v = s[i]; s[i] = run; run += v; }
    }
    __syncthreads();
    if (t < NB) g_bsum[t] = s[t];
}

__global__ void k_scanC() {
    int i = blockIdx.x * 256 + threadIdx.x;
    if (i < NN) {
        g_base[i] += g_bsum[i >> 10];
        g_cur[i] = 0;
        int d = g_deg[i];
        g_dinv[i] = 1.f / (float)(d > 1 ? d : 1);
    }
}

__global__ void k_fill(const int* __restrict__ ei) {
    int e = blockIdx.x * 256 + threadIdx.x;
    if (e < EE) {
        int is64 = g_is64;
        int src = is64 ? ei[2 * e]        : ei[e];
        int dst = is64 ? ei[2 * (EE + e)] : ei[EE + e];
        if ((unsigned)dst < NN && (unsigned)src < NN) {
            int r = atomicAdd(&g_cur[dst], 1);
            g_esrc[g_base[dst] + r] = src;
        }
    }
}

// ---------------- GEMM1: [P1|Q1] = x @ [W_l1|W_r1] (+b1 on Q half) -----------
// Tile 128 rows x 128 cols (P cols 0..63, Q cols 64..127), K=128 in 4x32 chunks.
// 256 threads, 8x8 micro-tiles. Static smem = 33.8 KB.
__global__ __launch_bounds__(256)
void k_gemm1(const float* __restrict__ x, const float* __restrict__ Wl,
             const float* __restrict__ Wr, const float* __restrict__ b1) {
    __shared__ float xsT[32][132];   // [k][row]
    __shared__ float Wc [32][132];   // [k][col 0..127]
    __shared__ float bs[64];

    const int tid   = threadIdx.x;
    const int rbase = blockIdx.x * 128;
    if (tid < 64) bs[tid] = b1[tid];

    const int ty = tid >> 4;   // 0..15 -> rows ty*8..+7
    const int tx = tid & 15;   // 0..15 -> cols tx*8..+7

    float acc[8][8];
    #pragma unroll
    for (int i = 0; i < 8; i++)
        #pragma unroll
        for (int j = 0; j < 8; j++) acc[i][j] = 0.f;

    const float4* x4  = (const float4*)x;   // row stride 32 float4
    const float4* wl4 = (const float4*)Wl;  // row stride 16 float4
    const float4* wr4 = (const float4*)Wr;

    #pragma unroll
    for (int chunk = 0; chunk < 4; chunk++) {
        // x chunk [128 rows][32 k] transposed: 1024 float4, 4/thread
        #pragma unroll
        for (int l = 0; l < 4; l++) {
            int idx = tid + l * 256;
            int row = idx >> 3;
            int k4  = idx & 7;
            float4 v = make_float4(0.f, 0.f, 0.f, 0.f);
            int gr = rbase + row;
            if (gr < NN) v = x4[gr * 32 + chunk * 8 + k4];
            int k = k4 * 4;
            xsT[k + 0][row] = v.x;
            xsT[k + 1][row] = v.y;
            xsT[k + 2][row] = v.z;
            xsT[k + 3][row] = v.w;
        }
        // W chunk [32 k][128 c]: 1024 float4, 4/thread (c4<16 -> Wl, else Wr)
        #pragma unroll
        for (int l = 0; l < 4; l++) {
            int idx = tid + l * 256;
            int k  = idx >> 5;
            int c4 = idx & 31;
            int gk = chunk * 32 + k;
            float4 v = (c4 < 16) ? wl4[gk * 16 + c4] : wr4[gk * 16 + (c4 - 16)];
            *(float4*)&Wc[k][c4 * 4] = v;
        }
        __syncthreads();

        #pragma unroll
        for (int k = 0; k < 32; k++) {
            float4 xa = *(const float4*)&xsT[k][ty * 8];
            float4 xb = *(const float4*)&xsT[k][ty * 8 + 4];
            float4 wa = *(const float4*)&Wc[k][tx * 8];
            float4 wb = *(const float4*)&Wc[k][tx * 8 + 4];
            float xv[8] = {xa.x, xa.y, xa.z, xa.w, xb.x, xb.y, xb.z, xb.w};
            float wv[8] = {wa.x, wa.y, wa.z, wa.w, wb.x, wb.y, wb.z, wb.w};
            #pragma unroll
            for (int i = 0; i < 8; i++)
                #pragma unroll
                for (int j = 0; j < 8; j++) acc[i][j] += xv[i] * wv[j];
        }
        __syncthreads();
    }

    const bool isQ = (tx >= 8);
    const int  cb  = isQ ? tx * 8 - 64 : tx * 8;
    float* outp    = isQ ? g_Q1 : g_P1;
    float bb[8] = {0.f,0.f,0.f,0.f,0.f,0.f,0.f,0.f};
    if (isQ) {
        #pragma unroll
        for (int j = 0; j < 8; j++) bb[j] = bs[cb + j];
    }
    #pragma unroll
    for (int i = 0; i < 8; i++) {
        int gr = rbase + ty * 8 + i;
        if (gr < NN) {
            *(float4*)&outp[gr * 64 + cb] =
                make_float4(acc[i][0] + bb[0], acc[i][1] + bb[1],
                            acc[i][2] + bb[2], acc[i][3] + bb[3]);
            *(float4*)&outp[gr * 64 + cb + 4] =
                make_float4(acc[i][4] + bb[4], acc[i][5] + bb[5],
                            acc[i][6] + bb[6], acc[i][7] + bb[7]);
        }
    }
}

// ---------------- agg1: warp-per-dst gather; h = leaky(sum*dinv + Q1) --------
__global__ __launch_bounds__(256)
void k_agg1() {
    int warp = (blockIdx.x * 256 + threadIdx.x) >> 5;
    int lane = threadIdx.x & 31;
    if (warp >= NN) return;
    int base = g_base[warp];
    int end  = base + g_deg[warp];
    float a0 = 0.f, a1 = 0.f, b0 = 0.f, b1 = 0.f;
    int j = base;
    for (; j + 1 < end; j += 2) {
        int s0 = g_esrc[j], s1 = g_esrc[j + 1];
        a0 += g_P1[s0 * 64 + lane];
        a1 += g_P1[s0 * 64 + 32 + lane];
        b0 += g_P1[s1 * 64 + lane];
        b1 += g_P1[s1 * 64 + 32 + lane];
    }
    if (j < end) {
        int s0 = g_esrc[j];
        a0 += g_P1[s0 * 64 + lane];
        a1 += g_P1[s0 * 64 + 32 + lane];
    }
    float di = g_dinv[warp];
    g_H[warp * 64 + lane]      = leaky((a0 + b0) * di + g_Q1[warp * 64 + lane]);
    g_H[warp * 64 + 32 + lane] = leaky((a1 + b1) * di + g_Q1[warp * 64 + 32 + lane]);
}

// ---------------- GEMM2: [P2|Q2] = H @ [W_l2|W_r2] (+b2 on Q half) -----------
// Tile 128 rows x 64 cols (P 0..31, Q 32..63), K=64 in 2x32 chunks. 256 thr,
// 8x4 micro-tiles. Static smem = 26 KB.
__global__ __launch_bounds__(256)
void k_gemm2(const float* __restrict__ Wl, const float* __restrict__ Wr,
             const float* __restrict__ b2) {
    __shared__ float hsT[32][132];  // [k][row]
    __shared__ float Wc [32][68];   // [k][col 0..63]
    __shared__ float bs[32];

    const int tid   = threadIdx.x;
    const int rbase = blockIdx.x * 128;
    if (tid < 32) bs[tid] = b2[tid];

    const int ty = tid >> 4;   // rows ty*8..+7
    const int tx = tid & 15;   // cols tx*4..+3

    float acc[8][4];
    #pragma unroll
    for (int i = 0; i < 8; i++)
        #pragma unroll
        for (int j = 0; j < 4; j++) acc[i][j] = 0.f;

    const float4* h4  = (const float4*)g_H;  // row stride 16 float4
    const float4* wl4 = (const float4*)Wl;   // row stride 8 float4
    const float4* wr4 = (const float4*)Wr;

    #pragma unroll
    for (int chunk = 0; chunk < 2; chunk++) {
        // H chunk [128 rows][32 k] transposed: 1024 float4, 4/thread
        #pragma unroll
        for (int l = 0; l < 4; l++) {
            int idx = tid + l * 256;
            int row = idx >> 3;
            int k4  = idx & 7;
            float4 v = make_float4(0.f, 0.f, 0.f, 0.f);
            int gr = rbase + row;
            if (gr < NN) v = h4[gr * 16 + chunk * 8 + k4];
            int k = k4 * 4;
            hsT[k + 0][row] = v.x;
            hsT[k + 1][row] = v.y;
            hsT[k + 2][row] = v.z;
            hsT[k + 3][row] = v.w;
        }
        // W chunk [32 k][64 c]: 512 float4, 2/thread (c4<8 -> Wl2, else Wr2)
        #pragma unroll
        for (int l = 0; l < 2; l++) {
            int idx = tid + l * 256;
            int k  = idx >> 4;
            int c4 = idx & 15;
            int gk = chunk * 32 + k;
            float4 v = (c4 < 8) ? wl4[gk * 8 + c4] : wr4[gk * 8 + (c4 - 8)];
            *(float4*)&Wc[k][c4 * 4] = v;
        }
        __syncthreads();

        #pragma unroll
        for (int k = 0; k < 32; k++) {
            float4 xa = *(const float4*)&hsT[k][ty * 8];
            float4 xb = *(const float4*)&hsT[k][ty * 8 + 4];
            float4 w  = *(const float4*)&Wc[k][tx * 4];
            float xv[8] = {xa.x, xa.y, xa.z, xa.w, xb.x, xb.y, xb.z, xb.w};
            float wv[4] = {w.x, w.y, w.z, w.w};
            #pragma unroll
            for (int i = 0; i < 8; i++)
                #pragma unroll
                for (int j = 0; j < 4; j++) acc[i][j] += xv[i] * wv[j];
        }
        __syncthreads();
    }

    const bool isQ = (tx >= 8);
    const int  cb  = isQ ? tx * 4 - 32 : tx * 4;
    float* outp    = isQ ? g_Q2 : g_P2;
    float bb[4] = {0.f, 0.f, 0.f, 0.f};
    if (isQ) {
        #pragma unroll
        for (int j = 0; j < 4; j++) bb[j] = bs[cb + j];
    }
    #pragma unroll
    for (int i = 0; i < 8; i++) {
        int gr = rbase + ty * 8 + i;
        if (gr < NN) {
            *(float4*)&outp[gr * 32 + cb] =
                make_float4(acc[i][0] + bb[0], acc[i][1] + bb[1],
                            acc[i][2] + bb[2], acc[i][3] + bb[3]);
        }
    }
}

// ---------------- agg2: warp-per-dst gather; out = leaky(sum*dinv + Q2) ------
__global__ __launch_bounds__(256)
void k_agg2(float* __restrict__ out) {
    int warp = (blockIdx.x * 256 + threadIdx.x) >> 5;
    int lane = threadIdx.x & 31;
    if (warp >= NN) return;
    int base = g_base[warp];
    int end  = base + g_deg[warp];
    float a = 0.f, b = 0.f;
    int j = base;
    for (; j + 1 < end; j += 2) {
        int s0 = g_esrc[j], s1 = g_esrc[j + 1];
        a += g_P2[s0 * 32 + lane];
        b += g_P2[s1 * 32 + lane];
    }
    if (j < end) a += g_P2[g_esrc[j] * 32 + lane];
    out[warp * 32 + lane] = leaky((a + b) * g_dinv[warp] + g_Q2[warp * 32 + lane]);
}

// ---------------- launch ------------------------------------------------------
extern "C" void kernel_launch(void* const* d_in, const int* in_sizes, int n_in,
                              void* d_out, int out_size) {
    const float* x   = (const float*)d_in[0];
    const int*   ei  = (const int*)d_in[1];     // int32 (JAX x64 off) or int64 — detected
    const float* Wl1 = (const float*)d_in[2];
    const float* Wr1 = (const float*)d_in[3];
    const float* b1  = (const float*)d_in[4];
    const float* Wl2 = (const float*)d_in[5];
    const float* Wr2 = (const float*)d_in[6];
    const float* b2  = (const float*)d_in[7];
    float* out = (float*)d_out;

    // CSR build
    k_detect<<<1, 64>>>(ei);
    k_zero  <<<(NN + 255) / 256, 256>>>();
    k_deg   <<<(EE + 255) / 256, 256>>>(ei);
    k_scanA <<<NB, 1024>>>();
    k_scanB <<<1, 128>>>();
    k_scanC <<<(NN + 255) / 256, 256>>>();
    k_fill  <<<(EE + 255) / 256, 256>>>(ei);

    // layer 1
    k_gemm1<<<(NN + 127) / 128, 256>>>(x, Wl1, Wr1, b1);
    k_agg1 <<<(NN * 32 + 255) / 256, 256>>>();

    // layer 2
    k_gemm2<<<(NN + 127) / 128, 256>>>(Wl2, Wr2, b2);
    k_agg2 <<<(NN * 32 + 255) / 256, 256>>>(out);
}

// round 14
// speedup vs baseline: 1.5643x; 1.5643x over previous
#include <cuda_runtime.h>
#include <mma.h>
using namespace nvcuda;

#define NN 100000
#define EE 1600000
#define NB 98            // ceil(NN/1024)
#define NPAD 100096      // 782 * 128, row padding for unguarded wmma stores

// ---------------- scratch (device globals; no allocation allowed) ------------
__device__ int                    g_is64;           // edge_index stored as int64?
__device__ int                    g_deg[NN];
__device__ int                    g_base[NN];       // CSR row offsets
__device__ int                    g_cur[NN];        // fill cursors
__device__ int                    g_bsum[NB];       // scan block sums
__device__ float                  g_dinv[NN];
__device__ int                    g_esrc[EE];       // src ids bucketed by dst
__device__ __align__(16) float    g_P1[NPAD * 64];  // x @ W_l1
__device__ __align__(16) float    g_Q1[NPAD * 64];  // x @ W_r1 (no bias)
__device__ __align__(16) float    g_H [NPAD * 64];  // layer-1 output (padding stays 0)
__device__ __align__(16) float    g_P2[NPAD * 32];  // h @ W_l2
__device__ __align__(16) float    g_Q2[NPAD * 32];  // h @ W_r2 (no bias)

__device__ __forceinline__ float leaky(float v) { return v > 0.f ? v : 0.1f * v; }

// ---------------- zero degree + dtype detect (fused) -------------------------
__global__ void k_zero(const int* __restrict__ ei) {
    int i = blockIdx.x * 256 + threadIdx.x;
    if (i < NN) g_deg[i] = 0;
    if (blockIdx.x == 0) {
        __shared__ int s[64];
        if (threadIdx.x < 64) s[threadIdx.x] = ei[2 * threadIdx.x + 1];
        __syncthreads();
        if (threadIdx.x == 0) {
            int acc = 0;
            #pragma unroll
            for (int t = 0; t < 64; t++) acc |= s[t];
            g_is64 = (acc == 0) ? 1 : 0;
        }
    }
}

__global__ void k_deg(const int* __restrict__ ei) {
    int e = blockIdx.x * 256 + threadIdx.x;
    if (e < EE) {
        int dst = g_is64 ? ei[2 * (EE + e)] : ei[EE + e];
        if ((unsigned)dst < NN) atomicAdd(&g_deg[dst], 1);
    }
}

__global__ __launch_bounds__(1024)
void k_scanA() {
    __shared__ int s[1024];
    int i = blockIdx.x * 1024 + threadIdx.x;
    int v = (i < NN) ? g_deg[i] : 0;
    s[threadIdx.x] = v;
    __syncthreads();
    #pragma unroll
    for (int off = 1; off < 1024; off <<= 1) {
        int t = (threadIdx.x >= off) ? s[threadIdx.x - off] : 0;
        __syncthreads();
        s[threadIdx.x] += t;
        __syncthreads();
    }
    if (i < NN) g_base[i] = s[threadIdx.x] - v;
    if (threadIdx.x == 1023) g_bsum[blockIdx.x] = s[1023];
}

__global__ void k_scanB() {
    __shared__ int s[128];
    int t = threadIdx.x;
    s[t] = (t < NB) ? g_bsum[t] : 0;
    __syncthreads();
    if (t == 0) {
        int run = 0;
        for (int i = 0; i < NB; i++) { int v = s[i]; s[i] = run; run += v; }
    }
    __syncthreads();
    if (t < NB) g_bsum[t] = s[t];
}

__global__ void k_scanC() {
    int i = blockIdx.x * 256 + threadIdx.x;
    if (i < NN) {
        g_base[i] += g_bsum[i >> 10];
        g_cur[i] = 0;
        int d = g_deg[i];
        g_dinv[i] = 1.f / (float)(d > 1 ? d : 1);
    }
}

__global__ void k_fill(const int* __restrict__ ei) {
    int e = blockIdx.x * 256 + threadIdx.x;
    if (e < EE) {
        int is64 = g_is64;
        int src = is64 ? ei[2 * e]        : ei[e];
        int dst = is64 ? ei[2 * (EE + e)] : ei[EE + e];
        if ((unsigned)dst < NN && (unsigned)src < NN) {
            int r = atomicAdd(&g_cur[dst], 1);
            g_esrc[g_base[dst] + r] = src;
        }
    }
}

// ---------------- GEMM1 (wmma tf32): [P1|Q1] = x @ [W_l1|W_r1] ---------------
// Block tile 128x128, K=128 in 4x32 chunks. 8 warps (4M x 2N), warp 32x64.
__global__ __launch_bounds__(256)
void k_gemm1(const float* __restrict__ x, const float* __restrict__ Wl,
             const float* __restrict__ Wr) {
    __shared__ float As[128][40];    // [m][k], pad 40
    __shared__ float Ws[32][136];    // [k][n], pad 136

    const int tid   = threadIdx.x;
    const int rbase = blockIdx.x * 128;
    const int warpId = tid >> 5;
    const int wm = warpId >> 1;      // 0..3
    const int wn = warpId & 1;       // 0..1

    wmma::fragment<wmma::accumulator, 16, 16, 8, float> acc[2][4];
    #pragma unroll
    for (int i = 0; i < 2; i++)
        #pragma unroll
        for (int j = 0; j < 4; j++) wmma::fill_fragment(acc[i][j], 0.f);

    const float4* x4  = (const float4*)x;   // row stride 32 float4
    const float4* wl4 = (const float4*)Wl;  // row stride 16 float4
    const float4* wr4 = (const float4*)Wr;

    #pragma unroll
    for (int chunk = 0; chunk < 4; chunk++) {
        // x chunk [128 rows][32 k]: 1024 float4, 4/thread
        #pragma unroll
        for (int l = 0; l < 4; l++) {
            int idx = tid + l * 256;
            int row = idx >> 3;
            int k4  = idx & 7;
            float4 v = make_float4(0.f, 0.f, 0.f, 0.f);
            int gr = rbase + row;
            if (gr < NN) v = x4[gr * 32 + chunk * 8 + k4];
            *(float4*)&As[row][k4 * 4] = v;
        }
        // W chunk [32 k][128 n]: 1024 float4, 4/thread
        #pragma unroll
        for (int l = 0; l < 4; l++) {
            int idx = tid + l * 256;
            int k  = idx >> 5;
            int c4 = idx & 31;
            int gk = chunk * 32 + k;
            float4 v = (c4 < 16) ? wl4[gk * 16 + c4] : wr4[gk * 16 + (c4 - 16)];
            *(float4*)&Ws[k][c4 * 4] = v;
        }
        __syncthreads();

        #pragma unroll
        for (int kk = 0; kk < 32; kk += 8) {
            wmma::fragment<wmma::matrix_a, 16, 16, 8, wmma::precision::tf32, wmma::row_major> af[2];
            wmma::fragment<wmma::matrix_b, 16, 16, 8, wmma::precision::tf32, wmma::row_major> bf[4];
            #pragma unroll
            for (int i = 0; i < 2; i++) {
                wmma::load_matrix_sync(af[i], &As[wm * 32 + i * 16][kk], 40);
                #pragma unroll
                for (int e = 0; e < af[i].num_elements; e++)
                    af[i].x[e] = wmma::__float_to_tf32(af[i].x[e]);
            }
            #pragma unroll
            for (int j = 0; j < 4; j++) {
                wmma::load_matrix_sync(bf[j], &Ws[kk][wn * 64 + j * 16], 136);
                #pragma unroll
                for (int e = 0; e < bf[j].num_elements; e++)
                    bf[j].x[e] = wmma::__float_to_tf32(bf[j].x[e]);
            }
            #pragma unroll
            for (int i = 0; i < 2; i++)
                #pragma unroll
                for (int j = 0; j < 4; j++)
                    wmma::mma_sync(acc[i][j], af[i], bf[j], acc[i][j]);
        }
        __syncthreads();
    }

    float* outp = wn ? g_Q1 : g_P1;
    #pragma unroll
    for (int i = 0; i < 2; i++) {
        int gr = rbase + wm * 32 + i * 16;   // < NPAD always
        #pragma unroll
        for (int j = 0; j < 4; j++)
            wmma::store_matrix_sync(&outp[(size_t)gr * 64 + j * 16], acc[i][j],
                                    64, wmma::mem_row_major);
    }
}

// ---------------- agg1: warp-per-dst gather; h = leaky(sum*dinv + Q1 + b1) ---
__global__ __launch_bounds__(256)
void k_agg1(const float* __restrict__ b1v) {
    int warp = (blockIdx.x * 256 + threadIdx.x) >> 5;
    int lane = threadIdx.x & 31;
    if (warp >= NN) return;
    int base = g_base[warp];
    int end  = base + g_deg[warp];
    float a0 = 0.f, a1 = 0.f, b0 = 0.f, b1 = 0.f;
    int j = base;
    for (; j + 1 < end; j += 2) {
        int s0 = g_esrc[j], s1 = g_esrc[j + 1];
        a0 += g_P1[s0 * 64 + lane];
        a1 += g_P1[s0 * 64 + 32 + lane];
        b0 += g_P1[s1 * 64 + lane];
        b1 += g_P1[s1 * 64 + 32 + lane];
    }
    if (j < end) {
        int s0 = g_esrc[j];
        a0 += g_P1[s0 * 64 + lane];
        a1 += g_P1[s0 * 64 + 32 + lane];
    }
    float di = g_dinv[warp];
    g_H[warp * 64 + lane] =
        leaky((a0 + b0) * di + g_Q1[warp * 64 + lane] + b1v[lane]);
    g_H[warp * 64 + 32 + lane] =
        leaky((a1 + b1) * di + g_Q1[warp * 64 + 32 + lane] + b1v[32 + lane]);
}

// ---------------- GEMM2 (wmma tf32): [P2|Q2] = H @ [W_l2|W_r2] ---------------
// Block tile 128x64, K=64 in 2x32 chunks. 8 warps (4M x 2N), warp 32x32.
__global__ __launch_bounds__(256)
void k_gemm2(const float* __restrict__ Wl, const float* __restrict__ Wr) {
    __shared__ float Hs[128][40];   // [m][k]
    __shared__ float Ws[32][72];    // [k][n]

    const int tid   = threadIdx.x;
    const int rbase = blockIdx.x * 128;
    const int warpId = tid >> 5;
    const int wm = warpId >> 1;
    const int wn = warpId & 1;

    wmma::fragment<wmma::accumulator, 16, 16, 8, float> acc[2][2];
    #pragma unroll
    for (int i = 0; i < 2; i++)
        #pragma unroll
        for (int j = 0; j < 2; j++) wmma::fill_fragment(acc[i][j], 0.f);

    const float4* h4  = (const float4*)g_H;  // row stride 16 float4
    const float4* wl4 = (const float4*)Wl;   // row stride 8 float4
    const float4* wr4 = (const float4*)Wr;

    #pragma unroll
    for (int chunk = 0; chunk < 2; chunk++) {
        // H chunk [128 rows][32 k]: 1024 float4, 4/thread (padding rows are 0s)
        #pragma unroll
        for (int l = 0; l < 4; l++) {
            int idx = tid + l * 256;
            int row = idx >> 3;
            int k4  = idx & 7;
            int gr = rbase + row;
            *(float4*)&Hs[row][k4 * 4] = h4[(size_t)gr * 16 + chunk * 8 + k4];
        }
        // W chunk [32 k][64 n]: 512 float4, 2/thread
        #pragma unroll
        for (int l = 0; l < 2; l++) {
            int idx = tid + l * 256;
            int k  = idx >> 4;
            int c4 = idx & 15;
            int gk = chunk * 32 + k;
            float4 v = (c4 < 8) ? wl4[gk * 8 + c4] : wr4[gk * 8 + (c4 - 8)];
            *(float4*)&Ws[k][c4 * 4] = v;
        }
        __syncthreads();

        #pragma unroll
        for (int kk = 0; kk < 32; kk += 8) {
            wmma::fragment<wmma::matrix_a, 16, 16, 8, wmma::precision::tf32, wmma::row_major> af[2];
            wmma::fragment<wmma::matrix_b, 16, 16, 8, wmma::precision::tf32, wmma::row_major> bf[2];
            #pragma unroll
            for (int i = 0; i < 2; i++) {
                wmma::load_matrix_sync(af[i], &Hs[wm * 32 + i * 16][kk], 40);
                #pragma unroll
                for (int e = 0; e < af[i].num_elements; e++)
                    af[i].x[e] = wmma::__float_to_tf32(af[i].x[e]);
            }
            #pragma unroll
            for (int j = 0; j < 2; j++) {
                wmma::load_matrix_sync(bf[j], &Ws[kk][wn * 32 + j * 16], 72);
                #pragma unroll
                for (int e = 0; e < bf[j].num_elements; e++)
                    bf[j].x[e] = wmma::__float_to_tf32(bf[j].x[e]);
            }
            #pragma unroll
            for (int i = 0; i < 2; i++)
                #pragma unroll
                for (int j = 0; j < 2; j++)
                    wmma::mma_sync(acc[i][j], af[i], bf[j], acc[i][j]);
        }
        __syncthreads();
    }

    float* outp = wn ? g_Q2 : g_P2;
    #pragma unroll
    for (int i = 0; i < 2; i++) {
        int gr = rbase + wm * 32 + i * 16;
        #pragma unroll
        for (int j = 0; j < 2; j++)
            wmma::store_matrix_sync(&outp[(size_t)gr * 32 + j * 16], acc[i][j],
                                    32, wmma::mem_row_major);
    }
}

// ---------------- agg2: out = leaky(sum*dinv + Q2 + b2) ----------------------
__global__ __launch_bounds__(256)
void k_agg2(const float* __restrict__ b2v, float* __restrict__ out) {
    int warp = (blockIdx.x * 256 + threadIdx.x) >> 5;
    int lane = threadIdx.x & 31;
    if (warp >= NN) return;
    int base = g_base[warp];
    int end  = base + g_deg[warp];
    float a = 0.f, b = 0.f;
    int j = base;
    for (; j + 1 < end; j += 2) {
        int s0 = g_esrc[j], s1 = g_esrc[j + 1];
        a += g_P2[s0 * 32 + lane];
        b += g_P2[s1 * 32 + lane];
    }
    if (j < end) a += g_P2[g_esrc[j] * 32 + lane];
    out[warp * 32 + lane] =
        leaky((a + b) * g_dinv[warp] + g_Q2[warp * 32 + lane] + b2v[lane]);
}

// ---------------- launch ------------------------------------------------------
extern "C" void kernel_launch(void* const* d_in, const int* in_sizes, int n_in,
                              void* d_out, int out_size) {
    const float* x   = (const float*)d_in[0];
    const int*   ei  = (const int*)d_in[1];     // int32 (JAX x64 off) or int64 — detected
    const float* Wl1 = (const float*)d_in[2];
    const float* Wr1 = (const float*)d_in[3];
    const float* b1  = (const float*)d_in[4];
    const float* Wl2 = (const float*)d_in[5];
    const float* Wr2 = (const float*)d_in[6];
    const float* b2  = (const float*)d_in[7];
    float* out = (float*)d_out;

    // CSR build
    k_zero  <<<(NN + 255) / 256, 256>>>(ei);
    k_deg   <<<(EE + 255) / 256, 256>>>(ei);
    k_scanA <<<NB, 1024>>>();
    k_scanB <<<1, 128>>>();
    k_scanC <<<(NN + 255) / 256, 256>>>();
    k_fill  <<<(EE + 255) / 256, 256>>>(ei);

    // layer 1
    k_gemm1<<<NPAD / 128, 256>>>(x, Wl1, Wr1);
    k_agg1 <<<(NN * 32 + 255) / 256, 256>>>(b1);

    // layer 2
    k_gemm2<<<NPAD / 128, 256>>>(Wl2, Wr2);
    k_agg2 <<<(NN * 32 + 255) / 256, 256>>>(b2, out);
}